// round 11
// baseline (speedup 1.0000x reference)
#include <cuda_runtime.h>
#include <cuda_bf16.h>

#define NF    13776
#define KC    8
#define NT    256
#define RPB   16                  // receivers per block (2 per warp)
#define NBLK  (NF / RPB)          // 861 blocks, exact
#define T1J   128                 // tier-1 scan extent
#define CHW   1728                // tier-2 j's per warp region (54*32); 128+8*1728 >= NF

// ---------------- scratch (device globals; no allocs) ----------------
__device__ float4   g_lo[NF];          // AABB min; .w = face id0 (bits)
__device__ float4   g_hi[NF];          // AABB max; .w = face id1 (bits)
__device__ int      g_fc2[NF];         // face id2
__device__ float4   g_tri4[NF * 3];    // vertex k of face f at [f*3+k]
__device__ float    g_partial[NBLK];
__device__ unsigned g_done = 0;        // self-resetting ticket

__device__ __forceinline__ float min3(float a, float b, float c) { return fminf(a, fminf(b, c)); }
__device__ __forceinline__ float max3(float a, float b, float c) { return fmaxf(a, fmaxf(b, c)); }

// ---------------- kernel 1: build SoA AABBs + packed ids + triangles ----------------
__global__ void __launch_bounds__(256)
setup_kernel(const float* __restrict__ verts,
             const int*   __restrict__ faces) {
    int f = blockIdx.x * 256 + threadIdx.x;
    if (f >= NF) return;

    int i0 = faces[3 * f + 0];
    int i1 = faces[3 * f + 1];
    int i2 = faces[3 * f + 2];

    float ax = verts[3 * i0 + 0], ay = verts[3 * i0 + 1], az = verts[3 * i0 + 2];
    float bx = verts[3 * i1 + 0], by = verts[3 * i1 + 1], bz = verts[3 * i1 + 2];
    float cx = verts[3 * i2 + 0], cy = verts[3 * i2 + 1], cz = verts[3 * i2 + 2];

    g_tri4[f * 3 + 0] = make_float4(ax, ay, az, 0.0f);
    g_tri4[f * 3 + 1] = make_float4(bx, by, bz, 0.0f);
    g_tri4[f * 3 + 2] = make_float4(cx, cy, cz, 0.0f);

    g_lo[f] = make_float4(min3(ax, bx, cx), min3(ay, by, cy), min3(az, bz, cz),
                          __int_as_float(i0));
    g_hi[f] = make_float4(max3(ax, bx, cx), max3(ay, by, cy), max3(az, bz, cz),
                          __int_as_float(i1));
    g_fc2[f] = i2;
}

// ---------------- cone-field penalty (matches jnp fp32 math) ----------------
__device__ __forceinline__ float cone_pen(const float* __restrict__ s,
                                          const float* __restrict__ p) {
    float e0x = s[3] - s[0], e0y = s[4] - s[1], e0z = s[5] - s[2];
    float e1x = s[6] - s[0], e1y = s[7] - s[1], e1z = s[8] - s[2];
    float nx = e0y * e1z - e0z * e1y;
    float ny = e0z * e1x - e0x * e1z;
    float nz = e0x * e1y - e0y * e1x;
    float inv = 1.0f / (sqrtf(nx * nx + ny * ny + nz * nz) + 1e-8f);
    nx *= inv; ny *= inv; nz *= inv;
    float cx = (s[0] + s[3] + s[6]) * (1.0f / 3.0f);
    float cy = (s[1] + s[4] + s[7]) * (1.0f / 3.0f);
    float cz = (s[2] + s[5] + s[8]) * (1.0f / 3.0f);

    float acc = 0.0f;
#pragma unroll
    for (int v = 0; v < 3; ++v) {
        float ux = p[3 * v + 0] - cx;
        float uy = p[3 * v + 1] - cy;
        float uz = p[3 * v + 2] - cz;
        float h = ux * nx + uy * ny + uz * nz;
        float wx = ux - h * nx, wy = uy - h * ny, wz = uz - h * nz;
        float r = sqrtf(wx * wx + wy * wy + wz * wz);
        float radial = fmaxf(1.0f - 2.0f * r, 0.0f);
        float depth  = fmaxf(-h, 0.0f) + fmaxf(h, 0.0f) * __expf(-2.0f * h);
        float phi = radial * depth;
        acc += phi * phi;
    }
    return acc;
}

// AABB-overlap + no-shared-vertex test of face j against receiver (reg state)
__device__ __forceinline__ bool pair_ok(int j,
                                        const float4& rlo, const float4& rhi,
                                        int r0, int r1, int r2) {
    float4 jlo = g_lo[j];
    float4 jhi = g_hi[j];
    bool ok = (rlo.x <= jhi.x) & (jlo.x <= rhi.x) &
              (rlo.y <= jhi.y) & (jlo.y <= rhi.y) &
              (rlo.z <= jhi.z) & (jlo.z <= rhi.z);
    if (ok) {
        int j0 = __float_as_int(jlo.w);
        int j1 = __float_as_int(jhi.w);
        int j2 = g_fc2[j];
        bool sh = (r0 == j0) | (r0 == j1) | (r0 == j2) |
                  (r1 == j0) | (r1 == j1) | (r1 == j2) |
                  (r2 == j0) | (r2 == j1) | (r2 == j2);
        ok = !sh;
    }
    return ok;
}

// ---------------- kernel 2: broad (tiered) + narrow + reduce ----------------
__global__ void __launch_bounds__(NT)
fused_kernel(float* __restrict__ out) {
    const int t    = threadIdx.x;
    const int lane = t & 31;
    const int w    = t >> 5;
    const int blockBase = blockIdx.x * RPB;
    const int iA = blockBase + 2 * w;
    const int iB = iA + 1;

    __shared__ int   sPairs[RPB][KC];
    __shared__ int   sCnt[RPB];
    __shared__ int   sInc[RPB];
    __shared__ int   sNInc;
    __shared__ int   sWloc[NT / 32][KC];
    __shared__ int   sWcnt[NT / 32];
    __shared__ float ssum[NT / 32];
    __shared__ bool  sLast;

    if (t == 0) sNInc = 0;
    __syncthreads();

    // receiver state (broadcast loads)
    float4 rloA = g_lo[iA], rhiA = g_hi[iA];
    float4 rloB = g_lo[iB], rhiB = g_hi[iB];
    int a0 = __float_as_int(rloA.w), a1 = __float_as_int(rhiA.w), a2 = g_fc2[iA];
    int b0 = __float_as_int(rloB.w), b1 = __float_as_int(rhiB.w), b2 = g_fc2[iB];

    // ---- tier 1: warp ballot scan of first T1J faces (2 receivers/warp) ----
    int cntA = 0, cntB = 0;
    for (int base = 0; base < T1J && (cntA < KC || cntB < KC); base += 32) {
        int j = base + lane;
        float4 jlo = g_lo[j];
        float4 jhi = g_hi[j];
        int j0 = __float_as_int(jlo.w);
        int j1 = __float_as_int(jhi.w);
        int j2 = g_fc2[j];

        bool okA = (rloA.x <= jhi.x) & (jlo.x <= rhiA.x) &
                   (rloA.y <= jhi.y) & (jlo.y <= rhiA.y) &
                   (rloA.z <= jhi.z) & (jlo.z <= rhiA.z);
        bool okB = (rloB.x <= jhi.x) & (jlo.x <= rhiB.x) &
                   (rloB.y <= jhi.y) & (jlo.y <= rhiB.y) &
                   (rloB.z <= jhi.z) & (jlo.z <= rhiB.z);
        if (okA) {
            bool sh = (a0 == j0) | (a0 == j1) | (a0 == j2) |
                      (a1 == j0) | (a1 == j1) | (a1 == j2) |
                      (a2 == j0) | (a2 == j1) | (a2 == j2);
            okA = !sh;
        }
        if (okB) {
            bool sh = (b0 == j0) | (b0 == j1) | (b0 == j2) |
                      (b1 == j0) | (b1 == j1) | (b1 == j2) |
                      (b2 == j0) | (b2 == j1) | (b2 == j2);
            okB = !sh;
        }
        unsigned mA = __ballot_sync(0xffffffffu, okA);
        unsigned mB = __ballot_sync(0xffffffffu, okB);
        unsigned lt = (1u << lane) - 1u;
        int rkA = __popc(mA & lt);
        int rkB = __popc(mB & lt);
        if (okA && (cntA + rkA) < KC) sPairs[2 * w + 0][cntA + rkA] = j;
        if (okB && (cntB + rkB) < KC) sPairs[2 * w + 1][cntB + rkB] = j;
        cntA = min(KC, cntA + __popc(mA));
        cntB = min(KC, cntB + __popc(mB));
    }
    if (lane < KC) {
        if (lane >= cntA) sPairs[2 * w + 0][lane] = -1;
        if (lane >= cntB) sPairs[2 * w + 1][lane] = -1;
    }
    if (lane == 0) {
        sCnt[2 * w + 0] = cntA;
        sCnt[2 * w + 1] = cntB;
        if (cntA < KC) { int q = atomicAdd(&sNInc, 1); sInc[q] = 2 * w + 0; }
        if (cntB < KC) { int q = atomicAdd(&sNInc, 1); sInc[q] = 2 * w + 1; }
    }
    __syncthreads();

    // ---- tier 2 (rare): block-cooperative completion of straggler receivers ----
    const int ninc = sNInc;
    for (int q = 0; q < ninc; ++q) {
        int r = sInc[q];
        int i = blockBase + r;
        int cnt0 = sCnt[r];

        float4 rlo = g_lo[i], rhi = g_hi[i];
        int r0 = __float_as_int(rlo.w), r1 = __float_as_int(rhi.w), r2 = g_fc2[i];

        // warp w scans region [T1J + w*CHW, ...) with coalesced ballot steps
        int js = T1J + w * CHW;
        int je = min(js + CHW, NF);
        int wcnt = 0;
        for (int base = js; base < je && wcnt < KC; base += 32) {
            int j = base + lane;
            bool ok = (j < je) ? pair_ok(j, rlo, rhi, r0, r1, r2) : false;
            unsigned m = __ballot_sync(0xffffffffu, ok);
            int rk = __popc(m & ((1u << lane) - 1u));
            if (ok && (wcnt + rk) < KC) sWloc[w][wcnt + rk] = j;
            wcnt = min(KC, wcnt + __popc(m));
        }
        if (lane == 0) sWcnt[w] = wcnt;
        __syncthreads();

        // ascending cross-warp compaction (thread 0, <=8 appends)
        if (t == 0) {
            int cnt = cnt0;
            for (int ww = 0; ww < NT / 32 && cnt < KC; ++ww) {
                int c = sWcnt[ww];
                for (int k = 0; k < c && cnt < KC; ++k)
                    sPairs[r][cnt++] = sWloc[ww][k];
            }
        }
        __syncthreads();
    }

    // ---- narrow phase: 256 tasks, one per thread ----
    float acc = 0.0f;
    {
        int r = t >> 4;
        int k = (t >> 1) & 7;
        int i = blockBase + r;
        int j = sPairs[r][k];
        if (j >= 0) {
            float a[9], b[9];
            float4 v0 = g_tri4[i * 3 + 0], v1 = g_tri4[i * 3 + 1], v2 = g_tri4[i * 3 + 2];
            a[0] = v0.x; a[1] = v0.y; a[2] = v0.z;
            a[3] = v1.x; a[4] = v1.y; a[5] = v1.z;
            a[6] = v2.x; a[7] = v2.y; a[8] = v2.z;
            float4 u0 = g_tri4[j * 3 + 0], u1 = g_tri4[j * 3 + 1], u2 = g_tri4[j * 3 + 2];
            b[0] = u0.x; b[1] = u0.y; b[2] = u0.z;
            b[3] = u1.x; b[4] = u1.y; b[5] = u1.z;
            b[6] = u2.x; b[7] = u2.y; b[8] = u2.z;
            acc = (t & 1) ? cone_pen(b, a) : cone_pen(a, b);
        }
    }

    // ---- block reduce (fixed order) ----
#pragma unroll
    for (int off = 16; off > 0; off >>= 1)
        acc += __shfl_down_sync(0xffffffffu, acc, off);
    if (lane == 0) ssum[w] = acc;
    __syncthreads();
    if (t == 0) {
        float v = 0.0f;
#pragma unroll
        for (int qq = 0; qq < NT / 32; ++qq) v += ssum[qq];
        g_partial[blockIdx.x] = v;
        __threadfence();
        unsigned ticket = atomicAdd(&g_done, 1);
        bool last = (ticket == NBLK - 1);
        if (last) g_done = 0;                    // reset for next graph replay
        sLast = last;
    }
    __syncthreads();

    // ---- last finishing block: fixed-order final sum ----
    if (sLast) {
        float a = 0.0f;
        for (int b = t; b < NBLK; b += NT)
            a += g_partial[b];
#pragma unroll
        for (int off = 16; off > 0; off >>= 1)
            a += __shfl_down_sync(0xffffffffu, a, off);
        __shared__ float fsum[NT / 32];
        if (lane == 0) fsum[w] = a;
        __syncthreads();
        if (t == 0) {
            float v = 0.0f;
#pragma unroll
            for (int qq = 0; qq < NT / 32; ++qq) v += fsum[qq];
            out[0] = v;
        }
    }
}

// ---------------- launch ----------------
extern "C" void kernel_launch(void* const* d_in, const int* in_sizes, int n_in,
                              void* d_out, int out_size) {
    const float* verts = (const float*)d_in[0];
    const int*   faces = (const int*)d_in[1];
    float* out = (float*)d_out;

    setup_kernel<<<(NF + 255) / 256, 256>>>(verts, faces);
    fused_kernel<<<NBLK, NT>>>(out);
}